// round 16
// baseline (speedup 1.0000x reference)
#include <cuda_runtime.h>
#include <cuda_bf16.h>
#include <math.h>
#include <float.h>
#include <stdint.h>

// ---------------------------------------------------------------------------
// Informer: B=4, L=1024, DM=512, NH=8, HD=64, DFF=2048, SK=35, 2 layers
// ---------------------------------------------------------------------------
#define B_   4
#define L_   1024
#define DM   512
#define NH   8
#define HD   64
#define DFF  2048
#define SK   35
#define NTOK (B_*L_)   // 4096
#define SPLITK 4
#define GS 3           // cp.async pipeline stages
#define NBH  (B_*NH)   // 32

__device__ float g_x   [NTOK*DM];
__device__ float g_q   [NTOK*DM];
__device__ float g_k   [NTOK*DM];
__device__ float g_v   [NTOK*DM];
__device__ float g_ctx [NTOK*DM];
__device__ float g_ff  [NTOK*DFF];
__device__ float g_split[SPLITK*NTOK*DM];
__device__ float g_M   [NBH*L_];
__device__ float g_poolp[B_*8*DM];
__device__ __nv_bfloat16 g_qh[NTOK*DM];   // bf16 copies for sampling
__device__ __nv_bfloat16 g_kh[NTOK*DM];
// attention intermediates
__device__ int   g_top  [NBH*SK];
__device__ float g_qsel [NBH*SK*HD];
__device__ float g_vmp  [NBH*8*64];       // vmean partials
__device__ float g_pmax [NBH*SK*8];
__device__ float g_psum [NBH*8*SK];
__device__ float g_cpart[(size_t)NBH*8*SK*HD];
// pre-rounded (tf32-rna) weights: Wq|Wk|Wv|Wo (both layers each) then W1, W2
#define WR_TOTAL (4*2*DM*DM + 2*DM*DFF + 2*DFF*DM)
__device__ float g_wr[WR_TOTAL];

// ---------------------------------------------------------------------------
__device__ __forceinline__ float to_tf32(float x) {
    uint32_t u;
    asm("cvt.rna.tf32.f32 %0, %1;" : "=r"(u) : "f"(x));
    return __uint_as_float(u);
}

__device__ __forceinline__ void mma_tf32(float* c, const uint32_t* a,
                                         uint32_t b0, uint32_t b1) {
    asm volatile(
        "mma.sync.aligned.m16n8k8.row.col.f32.tf32.tf32.f32 "
        "{%0,%1,%2,%3},{%4,%5,%6,%7},{%8,%9},{%0,%1,%2,%3};"
        : "+f"(c[0]), "+f"(c[1]), "+f"(c[2]), "+f"(c[3])
        : "r"(a[0]), "r"(a[1]), "r"(a[2]), "r"(a[3]), "r"(b0), "r"(b1));
}

__device__ __forceinline__ void cp16(void* smem, const void* g) {
    uint32_t s = (uint32_t)__cvta_generic_to_shared(smem);
    asm volatile("cp.async.cg.shared.global [%0], [%1], 16;\n" :: "r"(s), "l"(g));
}
#define CP_COMMIT() asm volatile("cp.async.commit_group;\n" ::: "memory")
#define CP_WAIT1()  asm volatile("cp.async.wait_group 1;\n" ::: "memory")

// ---------------------------------------------------------------------------
// Fused prologue: embed+posenc (blocks 0..NTOK-1) and weight tf32-rounding.
// ---------------------------------------------------------------------------
#define RND_BLOCKS ((WR_TOTAL/4 + 511) / 512)

__global__ void prep_kernel(const float* __restrict__ src,
                            const float* __restrict__ Wemb,
                            const float* __restrict__ bemb,
                            const float* __restrict__ Wq, const float* __restrict__ Wk,
                            const float* __restrict__ Wv, const float* __restrict__ Wo,
                            const float* __restrict__ W1, const float* __restrict__ W2) {
    const int bx = blockIdx.x;
    if (bx < NTOK) {
        int row = bx;
        int l   = row & (L_-1);
        int d   = threadIdx.x;
        __shared__ float s[32];
        if (d < 32) s[d] = src[row*32 + d];
        __syncthreads();
        float acc = bemb[d];
        #pragma unroll
        for (int k = 0; k < 32; k++) acc += s[k] * Wemb[k*DM + d];
        int i2 = d & ~1;
        float div = expf(-(float)i2 * (9.210340371976184f / 512.0f));
        float ang = (float)l * div;
        acc += (d & 1) ? cosf(ang) : sinf(ang);
        g_x[row*DM + d] = to_tf32(acc);
    } else {
        const int QS = 2*DM*DM;
        int i4 = (bx - NTOK) * 512 + threadIdx.x;
        int f  = i4 * 4;
        if (f >= WR_TOTAL) return;
        const float* sp;
        int off;
        if      (f < QS)      { sp = Wq; off = f; }
        else if (f < 2*QS)    { sp = Wk; off = f - QS; }
        else if (f < 3*QS)    { sp = Wv; off = f - 2*QS; }
        else if (f < 4*QS)    { sp = Wo; off = f - 3*QS; }
        else if (f < 4*QS + 2*DM*DFF) { sp = W1; off = f - 4*QS; }
        else                  { sp = W2; off = f - 4*QS - 2*DM*DFF; }
        float4 v = *(const float4*)&sp[off];
        v.x = to_tf32(v.x); v.y = to_tf32(v.y); v.z = to_tf32(v.z); v.w = to_tf32(v.w);
        *(float4*)&g_wr[f] = v;
    }
}

// ---------------------------------------------------------------------------
// tf32 GEMM, cp.async 3-stage pipeline. Block tile 128x128x16, 128 threads
// (4 warps, 2m x 2n, warp tile 64x64 -> 1.0 LDS per MMA).
// ---------------------------------------------------------------------------
#define AS(s,m,k) As[(s)*2560 + (m)*20 + (k)]
#define BS(s,k,n) Bs[(s)*2176 + (k)*136 + (n)]
#define GEMM_SMEM ((GS*2560 + GS*2176) * 4)

__device__ __forceinline__ void issue_tile(
        float* As, float* Bs, const float* A, const float* W,
        int lda, int N, int m0, int n0, int k0, int s, int tid) {
    #pragma unroll
    for (int i = 0; i < 4; i++) {
        int f = tid + i*128;
        int ma = f >> 2, kc = (f & 3) << 2;
        cp16(&AS(s,ma,kc), A + (size_t)(m0+ma)*lda + k0 + kc);
        int kr = f >> 5, nc = (f & 31) << 2;
        cp16(&BS(s,kr,nc), W + (size_t)(k0+kr)*N + n0 + nc);
    }
}

template<bool GELU, bool RAW, bool RND>
__device__ __forceinline__ void gemm_body(
        const float* __restrict__ A, const float* __restrict__ W,
        const float* __restrict__ bias, const float* __restrict__ resid,
        float* __restrict__ C, __nv_bfloat16* __restrict__ Hout,
        int N, int K, int lda, int bx, int by) {
    extern __shared__ float gsm[];
    float* As = gsm;
    float* Bs = gsm + GS*2560;

    const int tid  = threadIdx.x;          // 128
    const int w    = tid >> 5;             // 0..3
    const int lane = tid & 31;
    const int grp  = lane >> 2;
    const int qd   = lane & 3;
    const int warp_m = (w & 1) * 64;
    const int warp_n = (w >> 1) * 64;
    const int m0 = by * 128;
    const int n0 = bx * 128;

    float acc[4][8][4];
    #pragma unroll
    for (int mi = 0; mi < 4; mi++)
        #pragma unroll
        for (int ni = 0; ni < 8; ni++)
            #pragma unroll
            for (int j = 0; j < 4; j++) acc[mi][ni][j] = 0.f;

    const int nt = K >> 4;

    issue_tile(As, Bs, A, W, lda, N, m0, n0, 0, 0, tid);  CP_COMMIT();
    issue_tile(As, Bs, A, W, lda, N, m0, n0, 16, 1, tid); CP_COMMIT();

    for (int t = 0; t < nt; t++) {
        CP_WAIT1();
        __syncthreads();
        const int s = t % GS;
        if (t + 2 < nt)
            issue_tile(As, Bs, A, W, lda, N, m0, n0, (t+2) << 4, (t+2) % GS, tid);
        CP_COMMIT();

        #pragma unroll
        for (int kk = 0; kk < 16; kk += 8) {
            uint32_t af[4][4];
            #pragma unroll
            for (int mi = 0; mi < 4; mi++) {
                int mb = warp_m + mi*16 + grp;
                af[mi][0] = __float_as_uint(AS(s, mb,   kk+qd));
                af[mi][1] = __float_as_uint(AS(s, mb+8, kk+qd));
                af[mi][2] = __float_as_uint(AS(s, mb,   kk+qd+4));
                af[mi][3] = __float_as_uint(AS(s, mb+8, kk+qd+4));
            }
            #pragma unroll
            for (int ni = 0; ni < 8; ni++) {
                int nb = warp_n + ni*8 + grp;
                uint32_t b0 = __float_as_uint(BS(s, kk+qd,   nb));
                uint32_t b1 = __float_as_uint(BS(s, kk+qd+4, nb));
                #pragma unroll
                for (int mi = 0; mi < 4; mi++)
                    mma_tf32(acc[mi][ni], af[mi], b0, b1);
            }
        }
    }

    #pragma unroll
    for (int mi = 0; mi < 4; mi++) {
        int r0 = m0 + warp_m + mi*16 + grp;
        #pragma unroll
        for (int ni = 0; ni < 8; ni++) {
            int c = n0 + warp_n + ni*8 + qd*2;
            float v0 = acc[mi][ni][0];
            float v1 = acc[mi][ni][1];
            float v2 = acc[mi][ni][2];
            float v3 = acc[mi][ni][3];
            if (!RAW) {
                float b0 = bias[c], b1 = bias[c+1];
                v0 += b0; v1 += b1; v2 += b0; v3 += b1;
                if (resid) {
                    v0 += resid[(size_t)r0*N + c];     v1 += resid[(size_t)r0*N + c + 1];
                    v2 += resid[(size_t)(r0+8)*N + c]; v3 += resid[(size_t)(r0+8)*N + c + 1];
                }
                if (GELU) {
                    v0 = 0.5f*v0*(1.0f + erff(v0*0.70710678118654752f));
                    v1 = 0.5f*v1*(1.0f + erff(v1*0.70710678118654752f));
                    v2 = 0.5f*v2*(1.0f + erff(v2*0.70710678118654752f));
                    v3 = 0.5f*v3*(1.0f + erff(v3*0.70710678118654752f));
                }
            }
            if (RND) {
                v0 = to_tf32(v0); v1 = to_tf32(v1);
                v2 = to_tf32(v2); v3 = to_tf32(v3);
            }
            *(float2*)&C[(size_t)r0*N + c]     = make_float2(v0, v1);
            *(float2*)&C[(size_t)(r0+8)*N + c] = make_float2(v2, v3);
            if (Hout) {
                *(__nv_bfloat162*)&Hout[(size_t)r0*N + c] =
                    __floats2bfloat162_rn(v0, v1);
                *(__nv_bfloat162*)&Hout[(size_t)(r0+8)*N + c] =
                    __floats2bfloat162_rn(v2, v3);
            }
        }
    }
}

template<bool GELU, bool RND>
__global__ void __launch_bounds__(128, 2)
gemm_tc(const float* __restrict__ A, const float* __restrict__ W,
        const float* __restrict__ bias, const float* __restrict__ resid,
        float* __restrict__ C, int N, int K) {
    gemm_body<GELU, false, RND>(A, W, bias, resid, C, nullptr, N, K, K,
                                blockIdx.x, blockIdx.y);
}

// Fused QKV: blockIdx.z selects projection; Q,K also dual-stored as bf16.
__global__ void __launch_bounds__(128, 2)
qkv_tc(const float* __restrict__ A, int layer,
       const float* __restrict__ bq, const float* __restrict__ bk,
       const float* __restrict__ bv,
       float* __restrict__ Q, float* __restrict__ Ko, float* __restrict__ V) {
    const float* W; const float* bias; float* C; __nv_bfloat16* H;
    const int QS = 2*DM*DM;
    size_t loff = (size_t)layer*DM*DM;
    if (blockIdx.z == 0)      { W = g_wr + loff;        bias = bq; C = Q;  H = g_qh; }
    else if (blockIdx.z == 1) { W = g_wr + QS + loff;   bias = bk; C = Ko; H = g_kh; }
    else                      { W = g_wr + 2*QS + loff; bias = bv; C = V;  H = nullptr; }
    gemm_body<false, false, false>(A, W, bias, nullptr, C, H, DM, DM, DM,
                                   blockIdx.x, blockIdx.y);
}

// Generic split-K partial GEMM: blockIdx.z = k-chunk of size KC.
template<int KC>
__global__ void __launch_bounds__(128, 2)
splitk_tc(const float* __restrict__ A, const float* __restrict__ W,
          int lda) {
    const int kc = blockIdx.z;
    gemm_body<false, true, false>(A + kc*KC, W + (size_t)kc*KC*DM,
                                  nullptr, nullptr,
                                  g_split + (size_t)kc*NTOK*DM,
                                  nullptr, DM, KC, lda, blockIdx.x, blockIdx.y);
}

// Fused split-K reduce + bias + residual + LayerNorm (output rounded).
template<int NS>
__global__ void reduce_ln_kernel(const float* __restrict__ bias,
                                 const float* __restrict__ resid,
                                 const float* __restrict__ g,
                                 const float* __restrict__ be,
                                 float* __restrict__ out) {
    int row = blockIdx.x;
    int t   = threadIdx.x;
    size_t o0 = (size_t)row*DM + t;
    size_t o1 = o0 + 256;
    float v0 = resid[o0] + bias[t];
    float v1 = resid[o1] + bias[t+256];
    #pragma unroll
    for (int s = 0; s < NS; s++) {
        v0 += g_split[(size_t)s*NTOK*DM + o0];
        v1 += g_split[(size_t)s*NTOK*DM + o1];
    }
    __shared__ float red[256];
    red[t] = v0 + v1; __syncthreads();
    for (int s = 128; s > 0; s >>= 1) { if (t < s) red[t] += red[t+s]; __syncthreads(); }
    float mean = red[0] * (1.0f/DM);
    __syncthreads();
    float d0 = v0 - mean, d1 = v1 - mean;
    red[t] = d0*d0 + d1*d1; __syncthreads();
    for (int s = 128; s > 0; s >>= 1) { if (t < s) red[t] += red[t+s]; __syncthreads(); }
    float rstd = rsqrtf(red[0] * (1.0f/DM) + 1e-5f);
    out[o0] = to_tf32(d0*rstd*g[t]     + be[t]);
    out[o1] = to_tf32(d1*rstd*g[t+256] + be[t+256]);
}

// ---------------------------------------------------------------------------
// Merged vmean partials (blocks 0..255) + sampled measure M (rest).
// ---------------------------------------------------------------------------
__global__ void __launch_bounds__(512)
vm_sample_kernel(const int* __restrict__ idxs) {
    const int bx = blockIdx.x;
    const int t  = threadIdx.x;
    if (bx < 256) {
        const int bh = bx >> 3;
        const int r  = bx & 7;
        const int b  = bh >> 3;
        const int h  = bh & 7;
        const int e  = t & 63, rr = t >> 6;
        float acc = 0.f;
        int base = r*128 + rr*16;
        for (int l = base; l < base + 16; l++)
            acc += g_v[(size_t)((b<<10) + l)*DM + h*HD + e];
        __shared__ float red[512];
        red[t] = acc;
        __syncthreads();
        if (t < 64) {
            float s = 0.f;
            #pragma unroll
            for (int i = 0; i < 8; i++) s += red[t + i*64];
            g_vmp[(bh*8 + r)*64 + t] = s;
        }
        return;
    }
    int lane = t & 31;
    int wg   = (bx - 256) * 16 + (t >> 5);
    if (wg >= NBH*L_) return;
    int i = wg & (L_-1);
    int h = (wg >> 10) & (NH-1);
    int b = wg >> 13;
    const int grp = lane >> 3;
    const int sub = lane & 7;

    const float4* Qr16 = (const float4*)&g_qh[(size_t)(b*L_ + i)*DM + h*HD];
    float4 qraw = Qr16[sub];
    uint32_t qa = __float_as_uint(qraw.x), qb = __float_as_uint(qraw.y);
    uint32_t qc = __float_as_uint(qraw.z), qd2 = __float_as_uint(qraw.w);
    float2 q0 = __bfloat1622float2(*(__nv_bfloat162*)&qa);
    float2 q1 = __bfloat1622float2(*(__nv_bfloat162*)&qb);
    float2 q2 = __bfloat1622float2(*(__nv_bfloat162*)&qc);
    float2 q3 = __bfloat1622float2(*(__nv_bfloat162*)&qd2);

    int idxA = idxs[i*SK + (lane < SK ? lane : 0)];
    int idxB = idxs[i*SK + ((32 + lane) < SK ? 32 + lane : 0)];

    float mx = -FLT_MAX, sm = 0.f;
    #pragma unroll
    for (int jj = 0; jj < 9; jj++) {
        int j = 4*jj + grp;
        int srcA = __shfl_sync(0xffffffffu, idxA, j & 31);
        int srcB = __shfl_sync(0xffffffffu, idxB, (j - 32) & 31);
        int src  = (j < 32) ? srcA : srcB;
        bool valid = (j < SK);
        float p = 0.f;
        if (valid) {
            const float4* Kr16 = (const float4*)&g_kh[(size_t)(b*L_ + src)*DM + h*HD];
            float4 kraw = Kr16[sub];
            uint32_t ka = __float_as_uint(kraw.x), kb = __float_as_uint(kraw.y);
            uint32_t kc = __float_as_uint(kraw.z), kd = __float_as_uint(kraw.w);
            float2 k0 = __bfloat1622float2(*(__nv_bfloat162*)&ka);
            float2 k1 = __bfloat1622float2(*(__nv_bfloat162*)&kb);
            float2 k2 = __bfloat1622float2(*(__nv_bfloat162*)&kc);
            float2 k3 = __bfloat1622float2(*(__nv_bfloat162*)&kd);
            p = q0.x*k0.x + q0.y*k0.y + q1.x*k1.x + q1.y*k1.y
              + q2.x*k2.x + q2.y*k2.y + q3.x*k3.x + q3.y*k3.y;
        }
        p += __shfl_xor_sync(0xffffffffu, p, 4);
        p += __shfl_xor_sync(0xffffffffu, p, 2);
        p += __shfl_xor_sync(0xffffffffu, p, 1);
        if (valid) { mx = fmaxf(mx, p); sm += p; }
    }
    mx = fmaxf(mx, __shfl_xor_sync(0xffffffffu, mx, 8));
    sm += __shfl_xor_sync(0xffffffffu, sm, 8);
    mx = fmaxf(mx, __shfl_xor_sync(0xffffffffu, mx, 16));
    sm += __shfl_xor_sync(0xffffffffu, sm, 16);
    if (lane == 0) g_M[(b*NH+h)*L_ + i] = mx - sm * (1.0f/SK);
}

// ---------------------------------------------------------------------------
// Merged ctx broadcast fill (blocks 0..255) + top-k/Qsel prep (blocks 256..287).
// Top-k: warp-0 register-resident radix select (no block barriers in select).
// ---------------------------------------------------------------------------
__device__ __forceinline__ uint32_t f2ord(float f) {
    uint32_t u = __float_as_uint(f);
    return (u & 0x80000000u) ? ~u : (u | 0x80000000u);
}

__global__ void __launch_bounds__(512)
fill_prep_kernel() {
    __shared__ __align__(16) float vm[64];
    __shared__ int ties[1024];
    __shared__ int s_gt, s_tn;
    __shared__ int tops[48];

    const int bx = blockIdx.x;
    const int t  = threadIdx.x;

    if (bx < 256) {
        const int bh = bx >> 3;
        const int r  = bx & 7;
        const int b  = bh >> 3;
        const int h  = bh & 7;
        if (t < 64) {
            float s = 0.f;
            #pragma unroll
            for (int i = 0; i < 8; i++) s += g_vmp[(bh*8 + i)*64 + t];
            vm[t] = to_tf32(s * (1.0f/L_));
        }
        __syncthreads();
        const float4* vm4 = (const float4*)vm;
        #pragma unroll
        for (int i = 0; i < 4; i++) {
            int f = t + i*512;
            int l = r*128 + (f >> 4), ev = f & 15;
            *(float4*)&g_ctx[(size_t)((b<<10) + l)*DM + h*HD + ev*4] = vm4[ev];
        }
        return;
    }

    // ---- top-k + Qsel gather (blocks 256..287), select by warp 0 only
    const int bh = bx - 256;
    const int b  = bh >> 3;
    const int h  = bh & 7;
    const int lane = t & 31;
    const int w  = t >> 5;

    if (w == 0) {
        uint32_t v[32];
        #pragma unroll
        for (int j = 0; j < 32; j++)
            v[j] = f2ord(g_M[bh*L_ + lane*32 + j]);
        uint32_t prefix = 0;
        int need = SK;
        for (int bit = 31; bit >= 0; --bit) {
            uint32_t cd = (prefix >> bit) | 1u;
            int c = 0;
            #pragma unroll
            for (int j = 0; j < 32; j++) c += ((v[j] >> bit) == cd);
            int tot = __reduce_add_sync(0xffffffffu, c);
            if (tot >= need) prefix |= (1u << bit);
            else             need -= tot;
        }
        if (lane == 0) { s_gt = 0; s_tn = 0; }
        __syncwarp();
        #pragma unroll
        for (int j = 0; j < 32; j++) {
            int gi = lane*32 + j;
            if (v[j] > prefix) tops[atomicAdd(&s_gt, 1)] = gi;
            else if (v[j] == prefix) ties[atomicAdd(&s_tn, 1)] = gi;
        }
        __syncwarp();
        if (lane == 0) {
            int base = s_gt, tn = s_tn;
            int need2 = SK - base;          // == remaining ties to take
            for (int sel = 0; sel < need2; sel++) {
                int bi = -1, bvv = 0x7fffffff;
                for (int j = 0; j < tn; j++)
                    if (ties[j] < bvv) { bvv = ties[j]; bi = j; }
                tops[base + sel] = bvv;
                ties[bi] = 0x7fffffff;
            }
        }
    }
    __syncthreads();
    if (t < SK) g_top[bh*SK + t] = tops[t];

    for (int f = t; f < SK*HD; f += 512) {
        int u = f >> 6, k = f & 63;
        g_qsel[bh*SK*HD + f] = g_q[(size_t)((b<<10) + tops[u])*DM + h*HD + k];
    }
}

// ---------------------------------------------------------------------------
// Merged score+softmax-partial+ctx-partial, flash-style per-st max.
// Grid (8, NBH), 256 threads, dynamic smem.
// ---------------------------------------------------------------------------
#define AF_SMEM_FLOATS (64*129 + SK*64 + SK*128)

__global__ void __launch_bounds__(256)
attn_fused2() {
    extern __shared__ float csm[];
    float* kt = csm;
    float* sq = kt + 64*129;
    float* ps = sq + SK*64;

    const int st = blockIdx.x;
    const int bh = blockIdx.y;
    const int b  = bh >> 3;
    const int h  = bh & 7;
    const int t  = threadIdx.x;
    const int lane = t & 31;
    const int w  = t >> 5;

    #pragma unroll
    for (int i = 0; i < 8; i++) {
        int f = t + i*256;
        int s = f >> 4, ec = (f & 15) << 2;
        float4 kv = *(const float4*)&g_k[(size_t)((b<<10) + st*128 + s)*DM + h*HD + ec];
        kt[(ec+0)*129 + s] = kv.x;
        kt[(ec+1)*129 + s] = kv.y;
        kt[(ec+2)*129 + s] = kv.z;
        kt[(ec+3)*129 + s] = kv.w;
    }
    for (int f = t; f < SK*HD; f += 256) sq[f] = g_qsel[bh*SK*HD + f];
    __syncthreads();

    float acc[5][4];
    #pragma unroll
    for (int jj = 0; jj < 5; jj++)
        #pragma unroll
        for (int r = 0; r < 4; r++) acc[jj][r] = 0.f;

    for (int k = 0; k < 64; k++) {
        float kv0 = kt[k*129 + lane];
        float kv1 = kt[k*129 + lane + 32];
        float kv2 = kt[k*129 + lane + 64];
        float kv3 = kt[k*129 + lane + 96];
        #pragma unroll
        for (int jj = 0; jj < 5; jj++) {
            int u = w + 8*jj;
            if (u < SK) {
                float qv = sq[u*HD + k];
                acc[jj][0] += qv*kv0; acc[jj][1] += qv*kv1;
                acc[jj][2] += qv*kv2; acc[jj][3] += qv*kv3;
            }
        }
    }

    #pragma unroll
    for (int jj = 0; jj < 5; jj++) {
        int u = w + 8*jj;
        if (u < SK) {
            float s0 = acc[jj][0]*0.125f, s1 = acc[jj][1]*0.125f;
            float s2 = acc[jj][2]*0.125f, s3 = acc[jj][3]*0.125f;
            float m = fmaxf(fmaxf(s0, s1), fmaxf(s2, s3));
            #pragma unroll
            for (int o = 16; o > 0; o >>= 1) m = fmaxf(m, __shfl_xor_sync(0xffffffffu, m, o));
            float e0 = expf(s0 - m), e1 = expf(s1 - m);
            float e2 = expf(s2 - m), e3 = expf(s3 - m);
            ps[u*128 + lane]      = e0;
            ps[u*128 + lane + 32] = e1;
            ps[u*128 + lane + 64] = e2;
            ps[u*128 + lane + 96] = e3;
            float ss = e0 + e1 + e2 + e3;
            #pragma unroll
            for (int o = 16; o > 0; o >>= 1) ss += __shfl_xor_sync(0xffffffffu, ss, o);
            if (lane == 0) {
                g_pmax[(bh*SK + u)*8 + st] = m;
                g_psum[(bh*8 + st)*SK + u] = ss;
            }
        }
    }
    __syncthreads();

    #pragma unroll
    for (int i = 0; i < 8; i++) {
        int f = t + i*256;
        int s = f >> 4, ec = (f & 15) << 2;
        float4 vv = *(const float4*)&g_v[(size_t)((b<<10) + st*128 + s)*DM + h*HD + ec];
        kt[(ec+0)*129 + s] = vv.x;
        kt[(ec+1)*129 + s] = vv.y;
        kt[(ec+2)*129 + s] = vv.z;
        kt[(ec+3)*129 + s] = vv.w;
    }
    __syncthreads();

    const int e  = t & 63;
    const int ug = t >> 6;
    float cacc[9];
    #pragma unroll
    for (int jj = 0; jj < 9; jj++) cacc[jj] = 0.f;
    for (int s = 0; s < 128; s++) {
        float v = kt[e*129 + s];
        #pragma unroll
        for (int jj = 0; jj < 9; jj++) {
            int u = ug + 4*jj;
            if (u < SK) cacc[jj] += ps[u*128 + s] * v;
        }
    }
    #pragma unroll
    for (int jj = 0; jj < 9; jj++) {
        int u = ug + 4*jj;
        if (u < SK) g_cpart[((size_t)(bh*8 + st)*SK + u)*HD + e] = cacc[jj];
    }
}

// ---------------------------------------------------------------------------
// Scatter with flash-style recombination. Grid NBH, 512 threads.
// ---------------------------------------------------------------------------
__global__ void __launch_bounds__(512)
attn_scatter() {
    __shared__ float coef[48][8];
    __shared__ float zinv[48];
    __shared__ int   tops[48];
    const int bh = blockIdx.x;
    const int b  = bh >> 3;
    const int h  = bh & 7;
    const int t  = threadIdx.x;

    if (t < SK) {
        float mm[8];
        float M = -FLT_MAX;
        #pragma unroll
        for (int st = 0; st < 8; st++) {
            mm[st] = g_pmax[(bh*SK + t)*8 + st];
            M = fmaxf(M, mm[st]);
        }
        float z = 0.f;
        #pragma unroll
        for (int st = 0; st < 8; st++) {
            float c = expf(mm[st] - M);
            coef[t][st] = c;
            z += c * g_psum[(bh*8 + st)*SK + t];
        }
        zinv[t] = 1.0f / z;
        tops[t] = g_top[bh*SK + t];
    }
    __syncthreads();

    const int e  = t & 63;
    const int ug = t >> 6;
    #pragma unroll
    for (int jj = 0; jj < 5; jj++) {
        int u = ug + 8*jj;
        if (u < SK) {
            float c = 0.f;
            #pragma unroll
            for (int st = 0; st < 8; st++)
                c += coef[u][st] * g_cpart[((size_t)(bh*8 + st)*SK + u)*HD + e];
            g_ctx[(size_t)((b<<10) + tops[u])*DM + h*HD + e] = to_tf32(c * zinv[u]);
        }
    }
}

// ---------------------------------------------------------------------------
// Fused final LayerNorm + mean-pool stage1. Grid (B_, 8), 512 threads.
// ---------------------------------------------------------------------------
__global__ void __launch_bounds__(512)
lnpool_kernel(const float* __restrict__ in,
              const float* __restrict__ g, const float* __restrict__ be) {
    __shared__ float part[16][512];
    const int b = blockIdx.x, r = blockIdx.y;
    const int t = threadIdx.x;
    const int lane = t & 31, w = t >> 5;

    float gj[16], bj[16];
    #pragma unroll
    for (int j = 0; j < 16; j++) {
        gj[j] = g[lane + 32*j];
        bj[j] = be[lane + 32*j];
    }

    float acc[16];
    #pragma unroll
    for (int j = 0; j < 16; j++) acc[j] = 0.f;

    for (int rr = 0; rr < 8; rr++) {
        int row = b*L_ + r*128 + w*8 + rr;
        float v[16];
        float s = 0.f;
        #pragma unroll
        for (int j = 0; j < 16; j++) {
            v[j] = in[(size_t)row*DM + lane + 32*j];
            s += v[j];
        }
        #pragma unroll
        for (int o = 16; o > 0; o >>= 1) s += __shfl_xor_sync(0xffffffffu, s, o);
        float mean = s * (1.0f/DM);
        float s2 = 0.f;
        #pragma unroll
        for (int j = 0; j < 16; j++) {
            float d = v[j] - mean;
            s2 += d*d;
        }
        #pragma unroll
        for (int o = 16; o > 0; o >>= 1) s2 += __shfl_xor_sync(0xffffffffu, s2, o);
        float rstd = rsqrtf(s2 * (1.0f/DM) + 1e-5f);
        #pragma unroll
        for (int j = 0; j < 16; j++)
            acc[j] += (v[j] - mean)*rstd*gj[j] + bj[j];
    }
    #pragma unroll
    for (int j = 0; j < 16; j++) part[w][lane + 32*j] = acc[j];
    __syncthreads();
    float s = 0.f;
    #pragma unroll
    for (int ww = 0; ww < 16; ww++) s += part[ww][t];
    g_poolp[(b*8 + r)*DM + t] = s;
}

// ---------------------------------------------------------------------------
// Fused pool stage 2 + classifier (warp per (b,c))
// ---------------------------------------------------------------------------
__global__ void poolcls_kernel(const float* __restrict__ Wc,
                               const float* __restrict__ bc,
                               float* __restrict__ out) {
    __shared__ float pooled[B_*DM];
    int t = threadIdx.x;
    int lane = t & 31, w = t >> 5;
    #pragma unroll
    for (int i = 0; i < 4; i++) {
        int f = t + i*512;
        int b = f >> 9, d = f & 511;
        float acc = 0.f;
        #pragma unroll
        for (int r = 0; r < 8; r++) acc += g_poolp[(b*8 + r)*DM + d];
        pooled[f] = acc * (1.0f/L_);
    }
    __syncthreads();
    for (int bcp = w; bcp < B_*10; bcp += 16) {
        int b = bcp / 10, c = bcp % 10;
        float acc = 0.f;
        for (int d = lane; d < DM; d += 32)
            acc += pooled[b*DM + d] * Wc[d*10 + c];
        #pragma unroll
        for (int o = 16; o > 0; o >>= 1) acc += __shfl_xor_sync(0xffffffffu, acc, o);
        if (lane == 0) out[bcp] = acc + bc[c];
    }
}

// ---------------------------------------------------------------------------
extern "C" void kernel_launch(void* const* d_in, const int* in_sizes, int n_in,
                              void* d_out, int out_size) {
    const float* src   = (const float*)d_in[0];
    const int*   idxs  = (const int*)  d_in[1];
    const float* Wemb  = (const float*)d_in[2];
    const float* bemb  = (const float*)d_in[3];
    const float* Wq    = (const float*)d_in[4];
    const float* bq    = (const float*)d_in[5];
    const float* Wk    = (const float*)d_in[6];
    const float* bk    = (const float*)d_in[7];
    const float* Wv    = (const float*)d_in[8];
    const float* bv    = (const float*)d_in[9];
    const float* Wo    = (const float*)d_in[10];
    const float* bo    = (const float*)d_in[11];
    const float* g1    = (const float*)d_in[12];
    const float* beta1 = (const float*)d_in[13];
    const float* W1    = (const float*)d_in[14];
    const float* bf1   = (const float*)d_in[15];
    const float* W2    = (const float*)d_in[16];
    const float* bf2   = (const float*)d_in[17];
    const float* g2    = (const float*)d_in[18];
    const float* beta2 = (const float*)d_in[19];
    const float* gf    = (const float*)d_in[20];
    const float* betaf = (const float*)d_in[21];
    const float* Wc    = (const float*)d_in[22];
    const float* bc    = (const float*)d_in[23];

    void *px_, *pq_, *pk_, *pv_, *pctx_, *pff_, *pwr_;
    cudaGetSymbolAddress(&px_,   g_x);
    cudaGetSymbolAddress(&pq_,   g_q);
    cudaGetSymbolAddress(&pk_,   g_k);
    cudaGetSymbolAddress(&pv_,   g_v);
    cudaGetSymbolAddress(&pctx_, g_ctx);
    cudaGetSymbolAddress(&pff_,  g_ff);
    cudaGetSymbolAddress(&pwr_,  g_wr);
    float* px   = (float*)px_;
    float* pq   = (float*)pq_;
    float* pk   = (float*)pk_;
    float* pv   = (float*)pv_;
    float* pctx = (float*)pctx_;
    float* pff  = (float*)pff_;
    float* pwr  = (float*)pwr_;

    const int af_smem = AF_SMEM_FLOATS * 4;
    static int configured = 0;
    if (!configured) {
        configured = 1;
        cudaFuncSetAttribute(attn_fused2, cudaFuncAttributeMaxDynamicSharedMemorySize, af_smem);
        cudaFuncSetAttribute((const void*)qkv_tc, cudaFuncAttributeMaxDynamicSharedMemorySize, GEMM_SMEM);
        cudaFuncSetAttribute((const void*)gemm_tc<false,false>, cudaFuncAttributeMaxDynamicSharedMemorySize, GEMM_SMEM);
        cudaFuncSetAttribute((const void*)gemm_tc<true,true>,   cudaFuncAttributeMaxDynamicSharedMemorySize, GEMM_SMEM);
        cudaFuncSetAttribute((const void*)splitk_tc<256>, cudaFuncAttributeMaxDynamicSharedMemorySize, GEMM_SMEM);
        cudaFuncSetAttribute((const void*)splitk_tc<512>, cudaFuncAttributeMaxDynamicSharedMemorySize, GEMM_SMEM);
    }

    const int QS = 2*DM*DM;
    prep_kernel<<<NTOK + RND_BLOCKS, 512>>>(src, Wemb, bemb, Wq, Wk, Wv, Wo, W1, W2);

    for (int l = 0; l < 2; l++) {
        const float* W1_l = pwr + 4*QS + (size_t)l*DM*DFF;
        const float* W2_l = pwr + 4*QS + 2*DM*DFF + (size_t)l*DFF*DM;
        const float* Wo_l = pwr + 3*QS + (size_t)l*DM*DM;

        dim3 gQKV(DM/128, NTOK/128, 3);      // (4, 32, 3)
        dim3 gFF(DFF/128, NTOK/128);         // (16, 32)
        dim3 gWO(DM/128, NTOK/128, 2);       // (4, 32, 2) split-K2
        dim3 gSP(DM/128, NTOK/128, SPLITK);  // (4, 32, 4) split-K4
        dim3 gATT(8, NBH);                   // (8, 32)

        qkv_tc<<<gQKV, 128, GEMM_SMEM>>>(px, l, bq + l*DM, bk + l*DM, bv + l*DM,
                                         pq, pk, pv);

        vm_sample_kernel<<<256 + 2048, 512>>>(idxs + (size_t)l*L_*SK);
        fill_prep_kernel<<<256 + NBH, 512>>>();
        attn_fused2<<<gATT, 256, af_smem>>>();
        attn_scatter<<<NBH, 512>>>();

        splitk_tc<256><<<gWO, 128, GEMM_SMEM>>>(pctx, Wo_l, DM);
        reduce_ln_kernel<2><<<NTOK, 256>>>(bo + l*DM, px, g1 + l*DM, beta1 + l*DM, px);

        gemm_tc<true,true><<<gFF, 128, GEMM_SMEM>>>(px, W1_l, bf1 + l*DFF, nullptr, pff, DFF, DM);
        splitk_tc<512><<<gSP, 128, GEMM_SMEM>>>(pff, W2_l, DFF);
        reduce_ln_kernel<4><<<NTOK, 256>>>(bf2 + l*DM, px, g2 + l*DM, beta2 + l*DM, px);
    }

    lnpool_kernel<<<dim3(B_, 8), 512>>>(px, gf, betaf);
    poolcls_kernel<<<1, 512>>>(Wc, bc, (float*)d_out);
}

// round 17
// speedup vs baseline: 1.2354x; 1.2354x over previous
#include <cuda_runtime.h>
#include <cuda_bf16.h>
#include <math.h>
#include <float.h>
#include <stdint.h>

// ---------------------------------------------------------------------------
// Informer: B=4, L=1024, DM=512, NH=8, HD=64, DFF=2048, SK=35, 2 layers
// ---------------------------------------------------------------------------
#define B_   4
#define L_   1024
#define DM   512
#define NH   8
#define HD   64
#define DFF  2048
#define SK   35
#define NTOK (B_*L_)   // 4096
#define SPLITK 4
#define GS 3           // cp.async pipeline stages
#define NBH  (B_*NH)   // 32

__device__ float g_x   [NTOK*DM];
__device__ float g_q   [NTOK*DM];
__device__ float g_k   [NTOK*DM];
__device__ float g_v   [NTOK*DM];
__device__ float g_ctx [NTOK*DM];
__device__ float g_split[SPLITK*NTOK*DM];
__device__ float g_M   [NBH*L_];
__device__ float g_poolp[B_*8*DM];
__device__ __nv_bfloat16 g_qh[NTOK*DM];   // bf16 copies for sampling
__device__ __nv_bfloat16 g_kh[NTOK*DM];
__device__ __nv_bfloat16 g_xh[NTOK*DM];   // bf16 LN1 output (FF1 input)
__device__ __nv_bfloat16 g_ffh[NTOK*DFF]; // bf16 FF1 output (FF2 input)
// attention intermediates
__device__ int   g_top  [NBH*SK];
__device__ float g_qsel [NBH*SK*HD];
__device__ float g_vmp  [NBH*8*64];
__device__ float g_pmax [NBH*SK*8];
__device__ float g_psum [NBH*8*SK];
__device__ float g_cpart[(size_t)NBH*8*SK*HD];
// pre-rounded (tf32-rna) weights: Wq|Wk|Wv|Wo (both layers each)
#define WR_TOTAL (4*2*DM*DM)
__device__ float g_wr[WR_TOTAL];
// bf16 FF weights, k-pair interleaved words [K/2][N]: low half = even k
__device__ uint32_t g_w1h[2*(DM/2)*DFF];   // 2 x 256 x 2048
__device__ uint32_t g_w2h[2*(DFF/2)*DM];   // 2 x 1024 x 512

// ---------------------------------------------------------------------------
__device__ __forceinline__ float to_tf32(float x) {
    uint32_t u;
    asm("cvt.rna.tf32.f32 %0, %1;" : "=r"(u) : "f"(x));
    return __uint_as_float(u);
}

__device__ __forceinline__ void mma_tf32(float* c, const uint32_t* a,
                                         uint32_t b0, uint32_t b1) {
    asm volatile(
        "mma.sync.aligned.m16n8k8.row.col.f32.tf32.tf32.f32 "
        "{%0,%1,%2,%3},{%4,%5,%6,%7},{%8,%9},{%0,%1,%2,%3};"
        : "+f"(c[0]), "+f"(c[1]), "+f"(c[2]), "+f"(c[3])
        : "r"(a[0]), "r"(a[1]), "r"(a[2]), "r"(a[3]), "r"(b0), "r"(b1));
}

__device__ __forceinline__ void mma_bf16(float* c, const uint32_t* a,
                                         uint32_t b0, uint32_t b1) {
    asm volatile(
        "mma.sync.aligned.m16n8k16.row.col.f32.bf16.bf16.f32 "
        "{%0,%1,%2,%3},{%4,%5,%6,%7},{%8,%9},{%0,%1,%2,%3};"
        : "+f"(c[0]), "+f"(c[1]), "+f"(c[2]), "+f"(c[3])
        : "r"(a[0]), "r"(a[1]), "r"(a[2]), "r"(a[3]), "r"(b0), "r"(b1));
}

__device__ __forceinline__ void cp16(void* smem, const void* g) {
    uint32_t s = (uint32_t)__cvta_generic_to_shared(smem);
    asm volatile("cp.async.cg.shared.global [%0], [%1], 16;\n" :: "r"(s), "l"(g));
}
#define CP_COMMIT() asm volatile("cp.async.commit_group;\n" ::: "memory")
#define CP_WAIT1()  asm volatile("cp.async.wait_group 1;\n" ::: "memory")

// explicit pack: low 16 bits = first (even-k) element
__device__ __forceinline__ uint32_t packbf(float e, float o) {
    return ((uint32_t)__bfloat16_as_ushort(__float2bfloat16(o)) << 16)
         |  (uint32_t)__bfloat16_as_ushort(__float2bfloat16(e));
}

// ---------------------------------------------------------------------------
// Fused prologue: embed+posenc | tf32 QKV/Wo rounding | bf16 W1/W2 interleave
// ---------------------------------------------------------------------------
#define QW_BLOCKS 1024     // WR_TOTAL/4/512
#define W1_BLOCKS 512      // 2*(DM/2)*DFF/4/512
#define W2_BLOCKS 512

__global__ void prep_kernel(const float* __restrict__ src,
                            const float* __restrict__ Wemb,
                            const float* __restrict__ bemb,
                            const float* __restrict__ Wq, const float* __restrict__ Wk,
                            const float* __restrict__ Wv, const float* __restrict__ Wo,
                            const float* __restrict__ W1, const float* __restrict__ W2) {
    const int bx = blockIdx.x;
    const int t  = threadIdx.x;
    if (bx < NTOK) {
        int row = bx;
        int l   = row & (L_-1);
        int d   = t;
        __shared__ float s[32];
        if (d < 32) s[d] = src[row*32 + d];
        __syncthreads();
        float acc = bemb[d];
        #pragma unroll
        for (int k = 0; k < 32; k++) acc += s[k] * Wemb[k*DM + d];
        int i2 = d & ~1;
        float div = expf(-(float)i2 * (9.210340371976184f / 512.0f));
        float ang = (float)l * div;
        acc += (d & 1) ? cosf(ang) : sinf(ang);
        g_x[row*DM + d] = to_tf32(acc);
    } else if (bx < NTOK + QW_BLOCKS) {
        const int QS = 2*DM*DM;
        int f = ((bx - NTOK) * 512 + t) * 4;
        const float* sp; int off;
        if      (f < QS)      { sp = Wq; off = f; }
        else if (f < 2*QS)    { sp = Wk; off = f - QS; }
        else if (f < 3*QS)    { sp = Wv; off = f - 2*QS; }
        else                  { sp = Wo; off = f - 3*QS; }
        float4 v = *(const float4*)&sp[off];
        v.x = to_tf32(v.x); v.y = to_tf32(v.y); v.z = to_tf32(v.z); v.w = to_tf32(v.w);
        *(float4*)&g_wr[f] = v;
    } else if (bx < NTOK + QW_BLOCKS + W1_BLOCKS) {
        int wi = ((bx - NTOK - QW_BLOCKS) * 512 + t) * 4;   // word index
        int l   = wi >> 19;            // / (256*2048)
        int rem = wi & 524287;
        int k2  = rem >> 11;           // / 2048
        int n   = rem & 2047;
        const float* Wg = W1 + (size_t)l*DM*DFF;
        float4 ev = *(const float4*)&Wg[(size_t)(2*k2)*DFF + n];
        float4 od = *(const float4*)&Wg[(size_t)(2*k2+1)*DFF + n];
        uint4 o;
        o.x = packbf(ev.x, od.x); o.y = packbf(ev.y, od.y);
        o.z = packbf(ev.z, od.z); o.w = packbf(ev.w, od.w);
        *(uint4*)&g_w1h[wi] = o;
    } else {
        int wi = ((bx - NTOK - QW_BLOCKS - W1_BLOCKS) * 512 + t) * 4;
        int l   = wi >> 19;            // / (1024*512)
        int rem = wi & 524287;
        int k2  = rem >> 9;            // / 512
        int n   = rem & 511;
        const float* Wg = W2 + (size_t)l*DFF*DM;
        float4 ev = *(const float4*)&Wg[(size_t)(2*k2)*DM + n];
        float4 od = *(const float4*)&Wg[(size_t)(2*k2+1)*DM + n];
        uint4 o;
        o.x = packbf(ev.x, od.x); o.y = packbf(ev.y, od.y);
        o.z = packbf(ev.z, od.z); o.w = packbf(ev.w, od.w);
        *(uint4*)&g_w2h[wi] = o;
    }
}

// ---------------------------------------------------------------------------
// tf32 GEMM, cp.async 3-stage pipeline. Block tile 128x128x16, 128 threads.
// ---------------------------------------------------------------------------
#define AS(s,m,k) As[(s)*2560 + (m)*20 + (k)]
#define BS(s,k,n) Bs[(s)*2176 + (k)*136 + (n)]
#define GEMM_SMEM ((GS*2560 + GS*2176) * 4)

__device__ __forceinline__ void issue_tile(
        float* As, float* Bs, const float* A, const float* W,
        int lda, int N, int m0, int n0, int k0, int s, int tid) {
    #pragma unroll
    for (int i = 0; i < 4; i++) {
        int f = tid + i*128;
        int ma = f >> 2, kc = (f & 3) << 2;
        cp16(&AS(s,ma,kc), A + (size_t)(m0+ma)*lda + k0 + kc);
        int kr = f >> 5, nc = (f & 31) << 2;
        cp16(&BS(s,kr,nc), W + (size_t)(k0+kr)*N + n0 + nc);
    }
}

template<bool RAW>
__device__ __forceinline__ void gemm_body(
        const float* __restrict__ A, const float* __restrict__ W,
        const float* __restrict__ bias,
        float* __restrict__ C, __nv_bfloat16* __restrict__ Hout,
        int N, int K, int lda, int bx, int by) {
    extern __shared__ float gsm[];
    float* As = gsm;
    float* Bs = gsm + GS*2560;

    const int tid  = threadIdx.x;
    const int w    = tid >> 5;
    const int lane = tid & 31;
    const int grp  = lane >> 2;
    const int qd   = lane & 3;
    const int warp_m = (w & 1) * 64;
    const int warp_n = (w >> 1) * 64;
    const int m0 = by * 128;
    const int n0 = bx * 128;

    float acc[4][8][4];
    #pragma unroll
    for (int mi = 0; mi < 4; mi++)
        #pragma unroll
        for (int ni = 0; ni < 8; ni++)
            #pragma unroll
            for (int j = 0; j < 4; j++) acc[mi][ni][j] = 0.f;

    const int nt = K >> 4;

    issue_tile(As, Bs, A, W, lda, N, m0, n0, 0, 0, tid);  CP_COMMIT();
    issue_tile(As, Bs, A, W, lda, N, m0, n0, 16, 1, tid); CP_COMMIT();

    for (int t = 0; t < nt; t++) {
        CP_WAIT1();
        __syncthreads();
        const int s = t % GS;
        if (t + 2 < nt)
            issue_tile(As, Bs, A, W, lda, N, m0, n0, (t+2) << 4, (t+2) % GS, tid);
        CP_COMMIT();

        #pragma unroll
        for (int kk = 0; kk < 16; kk += 8) {
            uint32_t af[4][4];
            #pragma unroll
            for (int mi = 0; mi < 4; mi++) {
                int mb = warp_m + mi*16 + grp;
                af[mi][0] = __float_as_uint(AS(s, mb,   kk+qd));
                af[mi][1] = __float_as_uint(AS(s, mb+8, kk+qd));
                af[mi][2] = __float_as_uint(AS(s, mb,   kk+qd+4));
                af[mi][3] = __float_as_uint(AS(s, mb+8, kk+qd+4));
            }
            #pragma unroll
            for (int ni = 0; ni < 8; ni++) {
                int nb = warp_n + ni*8 + grp;
                uint32_t b0 = __float_as_uint(BS(s, kk+qd,   nb));
                uint32_t b1 = __float_as_uint(BS(s, kk+qd+4, nb));
                #pragma unroll
                for (int mi = 0; mi < 4; mi++)
                    mma_tf32(acc[mi][ni], af[mi], b0, b1);
            }
        }
    }

    #pragma unroll
    for (int mi = 0; mi < 4; mi++) {
        int r0 = m0 + warp_m + mi*16 + grp;
        #pragma unroll
        for (int ni = 0; ni < 8; ni++) {
            int c = n0 + warp_n + ni*8 + qd*2;
            float v0 = acc[mi][ni][0];
            float v1 = acc[mi][ni][1];
            float v2 = acc[mi][ni][2];
            float v3 = acc[mi][ni][3];
            if (!RAW) {
                float b0 = bias[c], b1 = bias[c+1];
                v0 += b0; v1 += b1; v2 += b0; v3 += b1;
            }
            *(float2*)&C[(size_t)r0*N + c]     = make_float2(v0, v1);
            *(float2*)&C[(size_t)(r0+8)*N + c] = make_float2(v2, v3);
            if (Hout) {
                *(uint32_t*)&Hout[(size_t)r0*N + c]     = packbf(v0, v1);
                *(uint32_t*)&Hout[(size_t)(r0+8)*N + c] = packbf(v2, v3);
            }
        }
    }
}

// Fused QKV: blockIdx.z selects projection; Q,K also dual-stored as bf16.
__global__ void __launch_bounds__(128, 2)
qkv_tc(const float* __restrict__ A, int layer,
       const float* __restrict__ bq, const float* __restrict__ bk,
       const float* __restrict__ bv,
       float* __restrict__ Q, float* __restrict__ Ko, float* __restrict__ V) {
    const float* W; const float* bias; float* C; __nv_bfloat16* H;
    const int QS = 2*DM*DM;
    size_t loff = (size_t)layer*DM*DM;
    if (blockIdx.z == 0)      { W = g_wr + loff;        bias = bq; C = Q;  H = g_qh; }
    else if (blockIdx.z == 1) { W = g_wr + QS + loff;   bias = bk; C = Ko; H = g_kh; }
    else                      { W = g_wr + 2*QS + loff; bias = bv; C = V;  H = nullptr; }
    gemm_body<false>(A, W, bias, C, H, DM, DM, DM, blockIdx.x, blockIdx.y);
}

// Wo split-K partial GEMM: blockIdx.z = k-chunk of size 256.
__global__ void __launch_bounds__(128, 2)
wo_splitk(const float* __restrict__ A, const float* __restrict__ W) {
    const int kc = blockIdx.z;
    gemm_body<true>(A + kc*256, W + (size_t)kc*256*DM, nullptr,
                    g_split + (size_t)kc*NTOK*DM, nullptr,
                    DM, 256, DM, blockIdx.x, blockIdx.y);
}

// ---------------------------------------------------------------------------
// bf16 GEMM, cp.async 3-stage pipeline. Block tile 128x128x32 (halves),
// 128 threads, warp tile 64x64, mma.m16n8k16.bf16. Identical smem word
// indexing to the tf32 body (pairs along k packed into 32-bit words).
// ---------------------------------------------------------------------------
__device__ __forceinline__ void issue_tile_bf(
        float* As, float* Bs, const __nv_bfloat16* Ah, const uint32_t* Ww,
        int ldah, int Nw, int m0, int n0, int k0h, int s, int tid) {
    #pragma unroll
    for (int i = 0; i < 4; i++) {
        int f = tid + i*128;
        int ma = f >> 2, wq = (f & 3) << 2;        // word offsets 0,4,8,12
        cp16(&AS(s,ma,wq), Ah + (size_t)(m0+ma)*ldah + k0h + wq*2);
        int kr = f >> 5, nc = (f & 31) << 2;
        cp16(&BS(s,kr,nc), Ww + (size_t)((k0h >> 1) + kr)*Nw + n0 + nc);
    }
}

template<bool GELU, bool RAW>
__device__ __forceinline__ void gemm_bf16_body(
        const __nv_bfloat16* __restrict__ Ah, const uint32_t* __restrict__ Ww,
        const float* __restrict__ bias,
        float* __restrict__ Craw, __nv_bfloat16* __restrict__ Hout,
        int Nw, int K, int ldah, int bx, int by) {
    extern __shared__ float gsm[];
    float* As = gsm;
    float* Bs = gsm + GS*2560;

    const int tid  = threadIdx.x;
    const int w    = tid >> 5;
    const int lane = tid & 31;
    const int grp  = lane >> 2;
    const int qd   = lane & 3;
    const int warp_m = (w & 1) * 64;
    const int warp_n = (w >> 1) * 64;
    const int m0 = by * 128;
    const int n0 = bx * 128;

    float acc[4][8][4];
    #pragma unroll
    for (int mi = 0; mi < 4; mi++)
        #pragma unroll
        for (int ni = 0; ni < 8; ni++)
            #pragma unroll
            for (int j = 0; j < 4; j++) acc[mi][ni][j] = 0.f;

    const int nt = K >> 5;   // 32 halves per tile

    issue_tile_bf(As, Bs, Ah, Ww, ldah, Nw, m0, n0, 0,  0, tid); CP_COMMIT();
    issue_tile_bf(As, Bs, Ah, Ww, ldah, Nw, m0, n0, 32, 1, tid); CP_COMMIT();

    for (int t = 0; t < nt; t++) {
        CP_WAIT1();
        __syncthreads();
        const int s = t % GS;
        if (t + 2 < nt)
            issue_tile_bf(As, Bs, Ah, Ww, ldah, Nw, m0, n0, (t+2) << 5, (t+2) % GS, tid);
        CP_COMMIT();

        #pragma unroll
        for (int kkw = 0; kkw < 16; kkw += 8) {    // 2 k16 slices (word units)
            uint32_t af[4][4];
            #pragma unroll
            for (int mi = 0; mi < 4; mi++) {
                int mb = warp_m + mi*16 + grp;
                af[mi][0] = __float_as_uint(AS(s, mb,   kkw+qd));
                af[mi][1] = __float_as_uint(AS(s, mb+8, kkw+qd));
                af[mi][2] = __float_as_uint(AS(s, mb,   kkw+qd+4));
                af[mi][3] = __float_as_uint(AS(s, mb+8, kkw+qd+4));
            }
            #pragma unroll
            for (int ni = 0; ni < 8; ni++) {
                int nb = warp_n + ni*8 + grp;
                uint32_t b0 = __float_as_uint(BS(s, kkw+qd,   nb));
                uint32_t b1 = __float_as_uint(BS(s, kkw+qd+4, nb));
                #pragma unroll
                for (int mi = 0; mi < 4; mi++)
                    mma_bf16(acc[mi][ni], af[mi], b0, b1);
            }
        }
    }

    #pragma unroll
    for (int mi = 0; mi < 4; mi++) {
        int r0 = m0 + warp_m + mi*16 + grp;
        #pragma unroll
        for (int ni = 0; ni < 8; ni++) {
            int c = n0 + warp_n + ni*8 + qd*2;
            float v0 = acc[mi][ni][0];
            float v1 = acc[mi][ni][1];
            float v2 = acc[mi][ni][2];
            float v3 = acc[mi][ni][3];
            if (RAW) {
                *(float2*)&Craw[(size_t)r0*Nw + c]     = make_float2(v0, v1);
                *(float2*)&Craw[(size_t)(r0+8)*Nw + c] = make_float2(v2, v3);
            } else {
                float b0 = bias[c], b1 = bias[c+1];
                v0 += b0; v1 += b1; v2 += b0; v3 += b1;
                if (GELU) {
                    v0 = 0.5f*v0*(1.0f + erff(v0*0.70710678118654752f));
                    v1 = 0.5f*v1*(1.0f + erff(v1*0.70710678118654752f));
                    v2 = 0.5f*v2*(1.0f + erff(v2*0.70710678118654752f));
                    v3 = 0.5f*v3*(1.0f + erff(v3*0.70710678118654752f));
                }
                *(uint32_t*)&Hout[(size_t)r0*Nw + c]     = packbf(v0, v1);
                *(uint32_t*)&Hout[(size_t)(r0+8)*Nw + c] = packbf(v2, v3);
            }
        }
    }
}

// FF1: g_xh @ W1 + bias -> GELU -> bf16 g_ffh. Grid (16, 32).
__global__ void __launch_bounds__(128, 2)
ff1_bf16(int layer, const float* __restrict__ bf1_) {
    gemm_bf16_body<true, false>(g_xh, g_w1h + (size_t)layer*(DM/2)*DFF,
                                bf1_, nullptr, g_ffh,
                                DFF, DM, DM, blockIdx.x, blockIdx.y);
}

// FF2 split-K: g_ffh @ W2 partials -> g_split. Grid (4, 32, 4).
__global__ void __launch_bounds__(128, 2)
ff2_bf16(int layer) {
    const int kc = blockIdx.z;
    gemm_bf16_body<false, true>(g_ffh + kc*512,
                                g_w2h + (size_t)layer*(DFF/2)*DM + (size_t)(kc*256)*DM,
                                nullptr, g_split + (size_t)kc*NTOK*DM, nullptr,
                                DM, 512, DFF, blockIdx.x, blockIdx.y);
}

// ---------------------------------------------------------------------------
// Fused split-K reduce + bias + residual + LayerNorm (output rounded).
// BF: also dual-store bf16 output (FF1 input).
// ---------------------------------------------------------------------------
template<int NS, bool BF>
__global__ void reduce_ln_kernel(const float* __restrict__ bias,
                                 const float* __restrict__ resid,
                                 const float* __restrict__ g,
                                 const float* __restrict__ be,
                                 float* __restrict__ out) {
    int row = blockIdx.x;
    int t   = threadIdx.x;
    size_t o0 = (size_t)row*DM + t;
    size_t o1 = o0 + 256;
    float v0 = resid[o0] + bias[t];
    float v1 = resid[o1] + bias[t+256];
    #pragma unroll
    for (int s = 0; s < NS; s++) {
        v0 += g_split[(size_t)s*NTOK*DM + o0];
        v1 += g_split[(size_t)s*NTOK*DM + o1];
    }
    __shared__ float red[256];
    red[t] = v0 + v1; __syncthreads();
    for (int s = 128; s > 0; s >>= 1) { if (t < s) red[t] += red[t+s]; __syncthreads(); }
    float mean = red[0] * (1.0f/DM);
    __syncthreads();
    float d0 = v0 - mean, d1 = v1 - mean;
    red[t] = d0*d0 + d1*d1; __syncthreads();
    for (int s = 128; s > 0; s >>= 1) { if (t < s) red[t] += red[t+s]; __syncthreads(); }
    float rstd = rsqrtf(red[0] * (1.0f/DM) + 1e-5f);
    float r0 = d0*rstd*g[t]     + be[t];
    float r1 = d1*rstd*g[t+256] + be[t+256];
    out[o0] = to_tf32(r0);
    out[o1] = to_tf32(r1);
    if (BF) {
        g_xh[o0] = __float2bfloat16(r0);
        g_xh[o1] = __float2bfloat16(r1);
    }
}

// ---------------------------------------------------------------------------
// Merged vmean partials (blocks 0..255) + sampled measure M (rest).
// ---------------------------------------------------------------------------
__global__ void __launch_bounds__(512)
vm_sample_kernel(const int* __restrict__ idxs) {
    const int bx = blockIdx.x;
    const int t  = threadIdx.x;
    if (bx < 256) {
        const int bh = bx >> 3;
        const int r  = bx & 7;
        const int b  = bh >> 3;
        const int h  = bh & 7;
        const int e  = t & 63, rr = t >> 6;
        float acc = 0.f;
        int base = r*128 + rr*16;
        for (int l = base; l < base + 16; l++)
            acc += g_v[(size_t)((b<<10) + l)*DM + h*HD + e];
        __shared__ float red[512];
        red[t] = acc;
        __syncthreads();
        if (t < 64) {
            float s = 0.f;
            #pragma unroll
            for (int i = 0; i < 8; i++) s += red[t + i*64];
            g_vmp[(bh*8 + r)*64 + t] = s;
        }
        return;
    }
    int lane = t & 31;
    int wg   = (bx - 256) * 16 + (t >> 5);
    if (wg >= NBH*L_) return;
    int i = wg & (L_-1);
    int h = (wg >> 10) & (NH-1);
    int b = wg >> 13;
    const int grp = lane >> 3;
    const int sub = lane & 7;

    const float4* Qr16 = (const float4*)&g_qh[(size_t)(b*L_ + i)*DM + h*HD];
    float4 qraw = Qr16[sub];
    uint32_t qa = __float_as_uint(qraw.x), qb = __float_as_uint(qraw.y);
    uint32_t qc = __float_as_uint(qraw.z), qd2 = __float_as_uint(qraw.w);
    float2 q0 = __bfloat1622float2(*(__nv_bfloat162*)&qa);
    float2 q1 = __bfloat1622float2(*(__nv_bfloat162*)&qb);
    float2 q2 = __bfloat1622float2(*(__nv_bfloat162*)&qc);
    float2 q3 = __bfloat1622float2(*(__nv_bfloat162*)&qd2);

    int idxA = idxs[i*SK + (lane < SK ? lane : 0)];
    int idxB = idxs[i*SK + ((32 + lane) < SK ? 32 + lane : 0)];

    float mx = -FLT_MAX, sm = 0.f;
    #pragma unroll
    for (int jj = 0; jj < 9; jj++) {
        int j = 4*jj + grp;
        int srcA = __shfl_sync(0xffffffffu, idxA, j & 31);
        int srcB = __shfl_sync(0xffffffffu, idxB, (j - 32) & 31);
        int src  = (j < 32) ? srcA : srcB;
        bool valid = (j < SK);
        float p = 0.f;
        if (valid) {
            const float4* Kr16 = (const float4*)&g_kh[(size_t)(b*L_ + src)*DM + h*HD];
            float4 kraw = Kr16[sub];
            uint32_t ka = __float_as_uint(kraw.x), kb = __float_as_uint(kraw.y);
            uint32_t kc = __float_as_uint(kraw.z), kd = __float_as_uint(kraw.w);
            float2 k0 = __bfloat1622float2(*(__nv_bfloat162*)&ka);
            float2 k1 = __bfloat1622float2(*(__nv_bfloat162*)&kb);
            float2 k2 = __bfloat1622float2(*(__nv_bfloat162*)&kc);
            float2 k3 = __bfloat1622float2(*(__nv_bfloat162*)&kd);
            p = q0.x*k0.x + q0.y*k0.y + q1.x*k1.x + q1.y*k1.y
              + q2.x*k2.x + q2.y*k2.y + q3.x*k3.x + q3.y*k3.y;
        }
        p += __shfl_xor_sync(0xffffffffu, p, 4);
        p += __shfl_xor_sync(0xffffffffu, p, 2);
        p += __shfl_xor_sync(0xffffffffu, p, 1);
        if (valid) { mx = fmaxf(mx, p); sm += p; }
    }
    mx = fmaxf(mx, __shfl_xor_sync(0xffffffffu, mx, 8));
    sm += __shfl_xor_sync(0xffffffffu, sm, 8);
    mx = fmaxf(mx, __shfl_xor_sync(0xffffffffu, mx, 16));
    sm += __shfl_xor_sync(0xffffffffu, sm, 16);
    if (lane == 0) g_M[(b*NH+h)*L_ + i] = mx - sm * (1.0f/SK);
}

// ---------------------------------------------------------------------------
// Merged ctx broadcast fill (blocks 0..255) + top-k/Qsel prep (blocks 256..287).
// (round-13 block-wide radix select)
// ---------------------------------------------------------------------------
__device__ __forceinline__ uint32_t f2ord(float f) {
    uint32_t u = __float_as_uint(f);
    return (u & 0x80000000u) ? ~u : (u | 0x80000000u);
}

__global__ void __launch_bounds__(512)
fill_prep_kernel() {
    __shared__ __align__(16) float vm[64];
    __shared__ int ties[1024];
    __shared__ int s_cntA[32];
    __shared__ int s_gt, s_tn;
    __shared__ int tops[48];

    const int bx = blockIdx.x;
    const int t  = threadIdx.x;

    if (bx < 256) {
        const int bh = bx >> 3;
        const int r  = bx & 7;
        const int b  = bh >> 3;
        const int h  = bh & 7;
        if (t < 64) {
            float s = 0.f;
            #pragma unroll
            for (int i = 0; i < 8; i++) s += g_vmp[(bh*8 + i)*64 + t];
            vm[t] = to_tf32(s * (1.0f/L_));
        }
        __syncthreads();
        const float4* vm4 = (const float4*)vm;
        #pragma unroll
        for (int i = 0; i < 4; i++) {
            int f = t + i*512;
            int l = r*128 + (f >> 4), ev = f & 15;
            *(float4*)&g_ctx[(size_t)((b<<10) + l)*DM + h*HD + ev*4] = vm4[ev];
        }
        return;
    }

    const int bh = bx - 256;
    const int b  = bh >> 3;
    const int h  = bh & 7;
    const int lane = t & 31;

    uint32_t u0 = f2ord(g_M[bh*L_ + t]);
    uint32_t u1 = f2ord(g_M[bh*L_ + t + 512]);
    if (t < 32) s_cntA[t] = 0;
    if (t == 0) { s_gt = 0; s_tn = 0; }
    __syncthreads();
    uint32_t prefix = 0;
    int need = SK;
    for (int bit = 31; bit >= 0; --bit) {
        uint32_t cd = (prefix >> bit) | 1u;
        int c = ((u0 >> bit) == cd) + ((u1 >> bit) == cd);
        int ws = __reduce_add_sync(0xffffffffu, c);
        if (lane == 0 && ws) atomicAdd(&s_cntA[bit], ws);
        __syncthreads();
        int cnt = s_cntA[bit];
        if (cnt >= need) prefix |= (1u << bit);
        else             need -= cnt;
    }
    if (u0 > prefix) tops[atomicAdd(&s_gt, 1)] = t;
    else if (u0 == prefix) ties[atomicAdd(&s_tn, 1)] = t;
    if (u1 > prefix) tops[atomicAdd(&s_gt, 1)] = t + 512;
    else if (u1 == prefix) ties[atomicAdd(&s_tn, 1)] = t + 512;
    __syncthreads();
    if (t == 0) {
        int base = s_gt, tn = s_tn;
        for (int sel = 0; sel < need; sel++) {
            int bi = -1, bvv = 0x7fffffff;
            for (int j = 0; j < tn; j++)
                if (ties[j] < bvv) { bvv = ties[j]; bi = j; }
            tops[base + sel] = bvv;
            ties[bi] = 0x7fffffff;
        }
    }
    __syncthreads();
    if (t < SK) g_top[bh*SK + t] = tops[t];

    for (int f = t; f < SK*HD; f += 512) {
        int u = f >> 6, k = f & 63;
        g_qsel[bh*SK*HD + f] = g_q[(size_t)((b<<10) + tops[u])*DM + h*HD + k];
    }
}

// ---------------------------------------------------------------------------
// Merged score+softmax-partial+ctx-partial, flash-style per-st max.
// Grid (8, NBH), 256 threads, dynamic smem.
// ---------------------------------------------------------------------------
#define AF_SMEM_FLOATS (64*129 + SK*64 + SK*128)

__global__ void __launch_bounds__(256)
attn_fused2() {
    extern __shared__ float csm[];
    float* kt = csm;
    float* sq = kt + 64*129;
    float* ps = sq + SK*64;

    const int st = blockIdx.x;
    const int bh = blockIdx.y;
    const int b  = bh >> 3;
    const int h  = bh & 7;
    const int t  = threadIdx.x;
    const int lane = t & 31;
    const int w  = t >> 5;

    #pragma unroll
    for (int i = 0; i < 8; i++) {
        int f = t + i*256;
        int s = f >> 4, ec = (f & 15) << 2;
        float4 kv = *(const float4*)&g_k[(size_t)((b<<10) + st*128 + s)*DM + h*HD + ec];
        kt[(ec+0)*129 + s] = kv.x;
        kt[(ec+1)*129 + s] = kv.y;
        kt[(ec+2)*129 + s] = kv.z;
        kt[(ec+3)*129 + s] = kv.w;
    }
    for (int f = t; f < SK*HD; f += 256) sq[f] = g_qsel[bh*SK*HD + f];
    __syncthreads();

    float acc[5][4];
    #pragma unroll
    for (int jj = 0; jj < 5; jj++)
        #pragma unroll
        for (int r = 0; r < 4; r++) acc[jj][r] = 0.f;

    for (int k = 0; k < 64; k++) {
        float kv0 = kt[k*129 + lane];
        float kv1 = kt[k*129 + lane + 32];
        float kv2 = kt[k*129 + lane + 64];
        float kv3 = kt[k*129 + lane + 96];
        #pragma unroll
        for (int jj = 0; jj < 5; jj++) {
            int u = w + 8*jj;
            if (u < SK) {
                float qv = sq[u*HD + k];
                acc[jj][0] += qv*kv0; acc[jj][1] += qv*kv1;
                acc[jj][2] += qv*kv2; acc[jj][3] += qv*kv3;
            }
        }
    }

    #pragma unroll
    for (int jj = 0; jj < 5; jj++) {
        int u = w + 8*jj;
        if (u < SK) {
            float s0 = acc[jj][0]*0.125f, s1 = acc[jj][1]*0.125f;
            float s2 = acc[jj][2]*0.125f, s3 = acc[jj][3]*0.125f;
            float m = fmaxf(fmaxf(s0, s1), fmaxf(s2, s3));
            #pragma unroll
            for (int o = 16; o > 0; o >>= 1) m = fmaxf(m, __shfl_xor_sync(0xffffffffu, m, o));
            float e0 = expf(s0 - m), e1 = expf(s1 - m);
            float e2 = expf(s2 - m), e3 = expf(s3 - m);
            ps[u*128 + lane]      = e0;
            ps[u*128 + lane + 32] = e1;
            ps[u*128 + lane + 64] = e2;
            ps[u*128 + lane + 96] = e3;
            float ss = e0 + e1 + e2 + e3;
            #pragma unroll
            for (int o = 16; o > 0; o >>= 1) ss += __shfl_xor_sync(0xffffffffu, ss, o);
            if (lane == 0) {
                g_pmax[(bh*SK + u)*8 + st] = m;
                g_psum[(bh*8 + st)*SK + u] = ss;
            }
        }
    }
    __syncthreads();

    #pragma unroll
    for (int i = 0; i < 8; i++) {
        int f = t + i*256;
        int s = f >> 4, ec = (f & 15) << 2;
        float4 vv = *(const float4*)&g_v[(size_t)((b<<10) + st*128 + s)*DM + h*HD + ec];
        kt[(ec+0)*129 + s] = vv.x;
        kt[(ec+1)*129 + s] = vv.y;
        kt[(ec+2)*129 + s] = vv.z;
        kt[(ec+3)*129 + s] = vv.w;
    }
    __syncthreads();

    const int e  = t & 63;
    const int ug = t >> 6;
    float cacc[9];
    #pragma unroll
    for (int jj = 0; jj < 9; jj++) cacc[jj] = 0.f;
    for (int s = 0; s < 128; s++) {
        float v = kt[e*129 + s];
        #pragma unroll
        for (int jj = 0; jj < 9; jj++) {
            int u = ug + 4*jj;
            if (u < SK) cacc[jj] += ps[u*128 + s] * v;
        }
    }
    #pragma unroll
    for (int jj = 0; jj < 9; jj++) {
        int u = ug + 4*jj;
        if (u < SK) g_cpart[((size_t)(bh*8 + st)*SK + u)*HD + e] = cacc[jj];
    }
}

// ---------------------------------------------------------------------------
// Scatter with flash-style recombination. Grid NBH, 512 threads.
// ---------------------------------------------------------------------------
__global__ void __launch_bounds__(512)
attn_scatter() {
    __shared__ float coef[48][8];
    __shared__ float zinv[48];
    __shared__ int   tops[48];
    const int bh = blockIdx.x;
    const int b  = bh >> 3;
    const int h  = bh & 7;
    const int t  = threadIdx.x;

    if (t < SK) {
        float mm[8];
        float M = -FLT_MAX;
        #pragma unroll
        for (int st = 0; st < 8; st++) {
            mm[st] = g_pmax[(bh*SK + t)*8 + st];
            M = fmaxf(M, mm[st]);
        }
        float z = 0.f;
        #pragma unroll
        for (int st = 0; st < 8; st++) {
            float c = expf(mm[st] - M);
            coef[t][st] = c;
            z += c * g_psum[(bh*8 + st)*SK + t];
        }
        zinv[t] = 1.0f / z;
        tops[t] = g_top[bh*SK + t];
    }
    __syncthreads();

    const int e  = t & 63;
    const int ug = t >> 6;
    #pragma unroll
    for (int jj = 0; jj < 5; jj++) {
        int u = ug + 8*jj;
        if (u < SK) {
            float c = 0.f;
            #pragma unroll
            for (int st = 0; st < 8; st++)
                c += coef[u][st] * g_cpart[((size_t)(bh*8 + st)*SK + u)*HD + e];
            g_ctx[(size_t)((b<<10) + tops[u])*DM + h*HD + e] = to_tf32(c * zinv[u]);
        }
    }
}

// ---------------------------------------------------------------------------
// Fused final LayerNorm + mean-pool stage1. Grid (B_, 8), 512 threads.
// ---------------------------------------------------------------------------
__global__ void __launch_bounds__(512)
lnpool_kernel(const float* __restrict__ in,
              const float* __restrict__ g, const float* __restrict__ be) {
    __shared__ float part[16][512];
    const int b = blockIdx.x, r = blockIdx.y;
    const int t = threadIdx.x;
    const int lane = t & 31, w = t >> 5;

    float gj[16], bj[16];
    #pragma unroll
    for (int j = 0; j < 16; j++) {
        gj[j] = g[lane + 32*j];
        bj[j] = be[lane + 32*j];
    }

    float acc[16];
    #pragma unroll
    for (int j = 0; j < 16; j++) acc[j] = 0.f;

    for (int rr = 0; rr < 8; rr++) {
        int row = b*L_ + r*128 + w*8 + rr;
        float v[16];
        float s = 0.f;
        #pragma unroll
        for (int j = 0; j < 16; j++) {
            v[j] = in[(size_t)row*DM + lane + 32*j];
            s += v[j];
        }
        #pragma unroll
        for (int o = 16; o > 0; o >>= 1) s += __shfl_xor_sync(0xffffffffu, s, o);
        float mean = s * (1.0f/DM);
        float s2 = 0.f;
        #pragma unroll
        for (int j = 0; j < 16; j++) {
            float d = v[j] - mean;
            s2 += d*d;
        }
        #pragma unroll
        for (int o = 16; o > 0; o >>= 1) s2 += __shfl_xor_sync(0xffffffffu, s2, o);
        float rstd = rsqrtf(s2 * (1.0f/DM) + 1e-5f);
        #pragma unroll
        for (int j = 0; j < 16; j++)
            acc[j] += (v[j] - mean)*rstd*gj[j] + bj[j];
    }
    #pragma unroll
    for (int j = 0; j < 16; j++) part[w][lane + 32*j] = acc[j];
    __syncthreads();
    float s = 0.f;
    #pragma unroll
    for (int ww = 0; ww < 16; ww++) s += part[ww][t];
    g_poolp[(b*8 + r)*DM + t] = s;
}

// ---------------------------------------------------------------------------
// Fused pool stage 2 + classifier (warp per (b,c))
// ---------------------------------------------------------------------------
__global__ void poolcls_kernel(const float* __restrict__ Wc,
                               const float* __restrict__ bc,
                               float* __restrict__ out) {
    __shared__ float pooled[B_*DM];
    int t = threadIdx.x;
    int lane = t & 31, w = t >> 5;
    #pragma unroll
    for (int i = 0; i < 4; i++) {
        int f = t + i*512;
        int b = f >> 9, d = f & 511;
        float acc = 0.f;
        #pragma unroll
        for (int r = 0; r < 8; r++) acc += g_poolp[(b*8 + r)*DM + d];
        pooled[f] = acc * (1.0f/L_);
    }
    __syncthreads();
    for (int bcp = w; bcp < B_*10; bcp += 16) {
        int b = bcp / 10, c = bcp % 10;
        float acc = 0.f;
        for (int d = lane; d < DM; d += 32)
            acc += pooled[b*DM + d] * Wc[d*10 + c];
        #pragma unroll
        for (int o = 16; o > 0; o >>= 1) acc += __shfl_xor_sync(0xffffffffu, acc, o);
        if (lane == 0) out[bcp] = acc + bc[c];
    }
}

// ---------------------------------------------------------------------------
extern "C" void kernel_launch(void* const* d_in, const int* in_sizes, int n_in,
                              void* d_out, int out_size) {
    const float* src   = (const float*)d_in[0];
    const int*   idxs  = (const int*)  d_in[1];
    const float* Wemb  = (const float*)d_in[2];
    const float* bemb  = (const float*)d_in[3];
    const float* Wq    = (const float*)d_in[4];
    const float* bq    = (const float*)d_in[5];
    const float* Wk    = (const float*)d_in[6];
    const float* bk    = (const float*)d_in[7];
    const float* Wv    = (const float*)d_in[8];
    const float* bv    = (const float*)d_in[9];
    const float* Wo    = (const float*)d_in[10];
    const float* bo    = (const float*)d_in[11];
    const float* g1    = (const float*)d_in[12];
    const float* beta1 = (const float*)d_in[13];
    const float* W1    = (const float*)d_in[14];
    const float* bf1   = (const float*)d_in[15];
    const float* W2    = (const float*)d_in[16];
    const float* bf2   = (const float*)d_in[17];
    const float* g2    = (const float*)d_in[18];
    const float* beta2 = (const float*)d_in[19];
    const float* gf    = (const float*)d_in[20];
    const float* betaf = (const float*)d_in[21];
    const float* Wc    = (const float*)d_in[22];
    const float* bc    = (const float*)d_in[23];

    void *px_, *pq_, *pk_, *pv_, *pctx_, *pwr_;
    cudaGetSymbolAddress(&px_,   g_x);
    cudaGetSymbolAddress(&pq_,   g_q);
    cudaGetSymbolAddress(&pk_,   g_k);
    cudaGetSymbolAddress(&pv_,   g_v);
    cudaGetSymbolAddress(&pctx_, g_ctx);
    cudaGetSymbolAddress(&pwr_,  g_wr);
    float* px   = (float*)px_;
    float* pq   = (float*)pq_;
    float* pk   = (float*)pk_;
    float* pv   = (float*)pv_;
    float* pctx = (float*)pctx_;
    float* pwr  = (float*)pwr_;

    const int af_smem = AF_SMEM_FLOATS * 4;
    static int configured = 0;
    if (!configured) {
        configured = 1;
        cudaFuncSetAttribute(attn_fused2, cudaFuncAttributeMaxDynamicSharedMemorySize, af_smem);
        cudaFuncSetAttribute((const void*)qkv_tc,     cudaFuncAttributeMaxDynamicSharedMemorySize, GEMM_SMEM);
        cudaFuncSetAttribute((const void*)wo_splitk,  cudaFuncAttributeMaxDynamicSharedMemorySize, GEMM_SMEM);
        cudaFuncSetAttribute((const void*)ff1_bf16,   cudaFuncAttributeMaxDynamicSharedMemorySize, GEMM_SMEM);
        cudaFuncSetAttribute((const void*)ff2_bf16,   cudaFuncAttributeMaxDynamicSharedMemorySize, GEMM_SMEM);
    }

    const int QS = 2*DM*DM;
    prep_kernel<<<NTOK + QW_BLOCKS + W1_BLOCKS + W2_BLOCKS, 512>>>(
        src, Wemb, bemb, Wq, Wk, Wv, Wo, W1, W2);

    for (int l = 0; l < 2; l++) {
        const float* Wo_l = pwr + 3*QS + (size_t)l*DM*DM;

        dim3 gQKV(DM/128, NTOK/128, 3);      // (4, 32, 3)
        dim3 gFF1(DFF/128, NTOK/128);        // (16, 32)
        dim3 gWO(DM/128, NTOK/128, 2);       // (4, 32, 2) Wo split-K2
        dim3 gFF2(DM/128, NTOK/128, SPLITK); // (4, 32, 4) FF2 split-K4
        dim3 gATT(8, NBH);                   // (8, 32)

        qkv_tc<<<gQKV, 128, GEMM_SMEM>>>(px, l, bq + l*DM, bk + l*DM, bv + l*DM,
                                         pq, pk, pv);

        vm_sample_kernel<<<256 + 2048, 512>>>(idxs + (size_t)l*L_*SK);
        fill_prep_kernel<<<256 + NBH, 512>>>();
        attn_fused2<<<gATT, 256, af_smem>>>();
        attn_scatter<<<NBH, 512>>>();

        wo_splitk<<<gWO, 128, GEMM_SMEM>>>(pctx, Wo_l);
        reduce_ln_kernel<2, true><<<NTOK, 256>>>(bo + l*DM, px, g1 + l*DM, beta1 + l*DM, px);

        ff1_bf16<<<gFF1, 128, GEMM_SMEM>>>(l, bf1 + l*DFF);
        ff2_bf16<<<gFF2, 128, GEMM_SMEM>>>(l);
        reduce_ln_kernel<4, false><<<NTOK, 256>>>(bf2 + l*DM, px, g2 + l*DM, beta2 + l*DM, px);
    }

    lnpool_kernel<<<dim3(B_, 8), 512>>>(px, gf, betaf);
    poolcls_kernel<<<1, 512>>>(Wc, bc, (float*)d_out);
}